// round 11
// baseline (speedup 1.0000x reference)
#include <cuda_runtime.h>
#include <cstdint>

// Problem constants
#define B_  4
#define H_  12
#define N_  2048
#define D_  64
#define C_  768
#define BHND (B_*H_*N_*D_)

// Scratch (device globals — no allocation allowed)
__device__ float g_q[BHND];            // [b,h][n][d]  tf32, d-permuted
__device__ float g_k[BHND];            // [b,h][n][d]  tf32, d-permuted
__device__ float g_v[BHND];            // [b,h][d][n]  tf32, TRANSPOSED, keys NOT permuted
__device__ float g_att[B_*N_*C_];      // [b,n][c]     tf32, c-permuted
__device__ float g_xc[B_*N_*C_];       // x, tf32, k-permuted
__device__ float g_wqkvT[3*C_*C_];     // qkv_w transposed [2304][768], tf32, k-permuted
__device__ float g_wprojT[C_*C_];      // proj_w transposed [768][768], tf32, k-permuted

#define LOG2E 1.4426950408889634f

__device__ __forceinline__ float to_tf32(float x){
    uint32_t u = __float_as_uint(x);
    asm("cvt.rna.tf32.f32 %0, %0;" : "+r"(u));
    return __uint_as_float(u);
}
__device__ __forceinline__ float ex2(float x){
    float r;
    asm("ex2.approx.ftz.f32 %0, %1;" : "=f"(r) : "f"(x));
    return r;
}
__device__ __forceinline__ int perm8(int j){ return (j & ~7) + 2*(j&3) + ((j>>2)&1); }

__device__ __forceinline__ void cp_async16(float* smem_dst, const float* gsrc){
    uint32_t s = (uint32_t)__cvta_generic_to_shared(smem_dst);
    asm volatile("cp.async.cg.shared.global [%0], [%1], 16;\n" :: "r"(s), "l"(gsrc));
}
__device__ __forceinline__ void cp_commit(){ asm volatile("cp.async.commit_group;\n"); }
template<int NN>
__device__ __forceinline__ void cp_wait(){ asm volatile("cp.async.wait_group %0;\n" :: "n"(NN)); }

// D = A(16x8, row) * B(8x8, col) + D ; tf32 inputs, fp32 accum
__device__ __forceinline__ void mma8(float d[4], const float a[4], float b0, float b1){
    asm volatile(
        "mma.sync.aligned.m16n8k8.row.col.f32.tf32.tf32.f32 "
        "{%0,%1,%2,%3},{%4,%5,%6,%7},{%8,%9},{%0,%1,%2,%3};\n"
        : "+f"(d[0]), "+f"(d[1]), "+f"(d[2]), "+f"(d[3])
        : "r"(__float_as_uint(a[0])), "r"(__float_as_uint(a[1])),
          "r"(__float_as_uint(a[2])), "r"(__float_as_uint(a[3])),
          "r"(__float_as_uint(b0)),   "r"(__float_as_uint(b1)));
}

// ---------------------------------------------------------------------------
// Conversion kernels (one-time per launch)
// ---------------------------------------------------------------------------
__global__ void cvt_perm_rows(const float* __restrict__ in, float* __restrict__ out, int n8){
    int g = blockIdx.x*blockDim.x + threadIdx.x;
    if (g >= n8) return;
    const float4* p = (const float4*)(in + (size_t)g*8);
    float4 u = p[0], v = p[1];
    float vals[8] = {u.x,u.y,u.z,u.w,v.x,v.y,v.z,v.w};
    float* o = out + (size_t)g*8;
    #pragma unroll
    for (int j = 0; j < 8; j++) o[2*(j&3)+((j>>2)&1)] = to_tf32(vals[j]);
}
__global__ void cvt_perm_T(const float* __restrict__ w, float* __restrict__ wt, int K, int NO){
    int idx = blockIdx.x*blockDim.x + threadIdx.x;
    if (idx >= K*NO) return;
    int k = idx / NO, n = idx % NO;
    wt[(size_t)n*K + perm8(k)] = to_tf32(w[idx]);
}

// ---------------------------------------------------------------------------
// TF32 GEMM:  out = A[M,K] @ Wt[N,K]^T + bias   (A, Wt pre-tf32, k-permuted)
// CTA tile 128x96, 128 threads, 4 warps (2x2), warp tile 64x48.
// 3 CTAs/SM (12 warps) for latency hiding; 149 B smem per mma.
// mode 0: row-major fp32 store; mode 1: QKV scatter (q,k d-perm; v transposed)
// ---------------------------------------------------------------------------
#define GSTR 40
#define ABUF (128*GSTR)   // 5120 floats per A buffer
#define BBUF (96*GSTR)    // 3840 floats per B buffer

__global__ __launch_bounds__(128,3) void gemm_tf32_kernel(
    const float* __restrict__ A, const float* __restrict__ Wt,
    const float* __restrict__ bias, float* __restrict__ out,
    int M, int K, int NO, int mode)
{
    extern __shared__ float smem[];
    float* sA = smem;                 // [2][128*40]
    float* sB = smem + 2*ABUF;        // [2][96*40]

    const int tid  = threadIdx.x;
    const int lane = tid & 31;
    const int warp = tid >> 5;        // 0..3
    const int wm   = warp & 1;        // m offset wm*64
    const int wn   = warp >> 1;       // n offset wn*48
    const int m0   = blockIdx.y * 128;
    const int n0   = blockIdx.x * 96;
    const int R    = lane >> 2;
    const int t2   = (lane & 3) << 1;

    float acc[4][6][4];
    #pragma unroll
    for (int i = 0; i < 4; i++)
        #pragma unroll
        for (int j = 0; j < 6; j++)
            #pragma unroll
            for (int r = 0; r < 4; r++) acc[i][j][r] = 0.f;

    const int steps = K >> 5;

    auto load_step = [&](int k0, int buf){
        float* dA = sA + buf*ABUF;
        float* dB = sB + buf*BBUF;
        #pragma unroll
        for (int i = 0; i < 8; i++){
            int id  = tid + i*128;
            int row = id >> 3;            // 0..127
            int c4  = (id & 7) << 2;      // 0..28
            cp_async16(&dA[row*GSTR + c4], A  + (size_t)(m0 + row)*K + k0 + c4);
        }
        #pragma unroll
        for (int i = 0; i < 6; i++){
            int id  = tid + i*128;
            int row = id >> 3;            // 0..95
            int c4  = (id & 7) << 2;
            cp_async16(&dB[row*GSTR + c4], Wt + (size_t)(n0 + row)*K + k0 + c4);
        }
        cp_commit();
    };

    load_step(0, 0);
    load_step(32, 1);

    for (int it = 0; it < steps; it++){
        if (it + 1 < steps) cp_wait<1>(); else cp_wait<0>();
        __syncthreads();

        const float* cA = sA + (it & 1)*ABUF;
        const float* cB = sB + (it & 1)*BBUF;

        #pragma unroll
        for (int kk = 0; kk < 4; kk++){
            float af[4][4];
            #pragma unroll
            for (int mf = 0; mf < 4; mf++){
                int rbase = wm*64 + mf*16 + R;
                float2 p0 = *(const float2*)&cA[rbase*GSTR + kk*8 + t2];
                float2 p1 = *(const float2*)&cA[(rbase+8)*GSTR + kk*8 + t2];
                af[mf][0] = p0.x; af[mf][1] = p1.x; af[mf][2] = p0.y; af[mf][3] = p1.y;
            }
            #pragma unroll
            for (int nf = 0; nf < 6; nf++){
                float2 bp = *(const float2*)&cB[(wn*48 + nf*8 + R)*GSTR + kk*8 + t2];
                #pragma unroll
                for (int mf = 0; mf < 4; mf++)
                    mma8(acc[mf][nf], af[mf], bp.x, bp.y);
            }
        }
        __syncthreads();
        if (it + 2 < steps) load_step((it+2) << 5, it & 1);
    }

    // epilogue
    #pragma unroll
    for (int mf = 0; mf < 4; mf++){
        #pragma unroll
        for (int nf = 0; nf < 6; nf++){
            #pragma unroll
            for (int rr = 0; rr < 2; rr++){
                int gm  = m0 + wm*64 + mf*16 + R + rr*8;
                int gn0 = n0 + wn*48 + nf*8 + t2;
                float v0 = acc[mf][nf][rr*2+0] + bias[gn0];
                float v1 = acc[mf][nf][rr*2+1] + bias[gn0+1];
                if (mode == 0){
                    *(float2*)(out + (size_t)gm*NO + gn0) = make_float2(v0, v1);
                } else {
                    int three = gn0 / 768;
                    int rem   = gn0 % 768;
                    int h     = rem / 64;
                    int d     = rem & 63;
                    int b     = gm >> 11;
                    int n     = gm & 2047;
                    size_t bh = (size_t)(b*H_ + h);
                    if (three == 0){
                        size_t ro = (bh*N_ + n)*D_;
                        g_q[ro + perm8(d)]   = to_tf32(v0);
                        g_q[ro + perm8(d+1)] = to_tf32(v1);
                    } else if (three == 1){
                        size_t ro = (bh*N_ + n)*D_;
                        g_k[ro + perm8(d)]   = to_tf32(v0);
                        g_k[ro + perm8(d+1)] = to_tf32(v1);
                    } else {  // v: transposed [d][n], keys NOT permuted
                        size_t vo = (bh*D_ + d)*N_ + n;
                        g_v[vo]      = to_tf32(v0);
                        g_v[vo + N_] = to_tf32(v1);
                    }
                }
            }
        }
    }
}

// ---------------------------------------------------------------------------
// Fused attention: 128 q-rows/CTA, 8 warps x 16 rows, key tile 64.
// PV consumes the S accumulator fragment DIRECTLY as mma A-operand: the
// contraction-index bijection mu(c)=2(c&3)+((c>>2)&1) is absorbed by loading
// V^T (unpermuted keys) at positions (2t, 2t+1). Zero shuffles.
// ---------------------------------------------------------------------------
#define KSTR 72
#define KV_BUF (64*KSTR)
#define ASTR 72
#define NEG_INF __int_as_float(0xff800000)

__global__ __launch_bounds__(256,2) void attn_kernel(
    const float* __restrict__ alibi, const int* __restrict__ pmask)
{
    extern __shared__ float sm[];
    float* KsB = sm;                   // [2][64*72]
    float* VsB = sm + 2*KV_BUF;        // [2][64*72]
    float* ALs = sm + 4*KV_BUF;        // [128*72] alibi stage (warp-private rows)

    const int tid  = threadIdx.x;
    const int lane = tid & 31;
    const int warp = tid >> 5;
    const int q0 = blockIdx.x * 128;
    const int h  = blockIdx.y;
    const int b  = blockIdx.z;
    const int R  = lane >> 2;
    const int t2 = (lane & 3) << 1;

    const int r0 = q0 + warp*16 + R;
    const size_t bh = (size_t)(b*H_ + h);
    const float* qp = g_q + bh*N_*D_;

    const float qscale = 0.125f * LOG2E;
    float qa[8][4];
    #pragma unroll
    for (int ks = 0; ks < 8; ks++){
        float2 p0 = *(const float2*)&qp[(size_t)r0*64 + ks*8 + t2];
        float2 p1 = *(const float2*)&qp[(size_t)(r0+8)*64 + ks*8 + t2];
        qa[ks][0] = to_tf32(p0.x*qscale); qa[ks][1] = to_tf32(p1.x*qscale);
        qa[ks][2] = to_tf32(p0.y*qscale); qa[ks][3] = to_tf32(p1.y*qscale);
    }

    float o[8][4];
    #pragma unroll
    for (int nf = 0; nf < 8; nf++){ o[nf][0]=o[nf][1]=o[nf][2]=o[nf][3]=0.f; }
    float mrun0 = -1e30f, mrun1 = -1e30f, l0 = 0.f, l1 = 0.f;

    const float* kbase = g_k + bh*N_*D_;            // [key][d]
    const float* vbase = g_v + bh*(size_t)D_*N_;    // [d][key]
    const float* abase = alibi + (bh*N_ + q0 + warp*16)*(size_t)N_;
    const int* pm = pmask + b*N_;

    auto load_kv = [&](int j0, int buf){
        float* dK = KsB + buf*KV_BUF;
        float* dV = VsB + buf*KV_BUF;
        #pragma unroll
        for (int i = 0; i < 4; i++){
            int id  = tid + i*256;
            int row = id >> 4;
            int c4  = (id & 15) << 2;
            cp_async16(&dK[row*KSTR + c4], kbase + (size_t)(j0+row)*64 + c4);
            cp_async16(&dV[row*KSTR + c4], vbase + (size_t)row*N_ + j0 + c4);
        }
        cp_commit();
    };
    auto load_al = [&](int j0){
        #pragma unroll
        for (int i = 0; i < 8; i++){
            int id = i*32 + lane;
            int rr = id >> 4;
            int cc = (id & 15) << 2;
            cp_async16(&ALs[(warp*16 + rr)*ASTR + cc],
                       abase + (size_t)rr*N_ + j0 + cc);
        }
        cp_commit();
    };

    load_kv(0, 0);
    load_kv(64, 1);
    load_al(0);

    unsigned mlo = __ballot_sync(0xffffffffu, pm[lane]      != 0);
    unsigned mhi = __ballot_sync(0xffffffffu, pm[32 + lane] != 0);

    for (int it = 0; it < 32; it++){
        const int j0 = it << 6;
        if (it == 0 || it == 31) cp_wait<0>(); else cp_wait<1>();
        __syncthreads();

        const float* Ks = KsB + (it & 1)*KV_BUF;
        const float* Vs = VsB + (it & 1)*KV_BUF;

        // S init = alibi * log2e
        float s[8][4];
        #pragma unroll
        for (int nf = 0; nf < 8; nf++){
            int c = nf*8 + t2;
            float2 a0 = *(const float2*)&ALs[(warp*16 + R)*ASTR + c];
            float2 a1 = *(const float2*)&ALs[(warp*16 + R + 8)*ASTR + c];
            s[nf][0] = a0.x*LOG2E; s[nf][1] = a0.y*LOG2E;
            s[nf][2] = a1.x*LOG2E; s[nf][3] = a1.y*LOG2E;
        }

        // S += Q' @ K^T
        #pragma unroll
        for (int ks = 0; ks < 8; ks++){
            #pragma unroll
            for (int nf = 0; nf < 8; nf++){
                float2 bp = *(const float2*)&Ks[(nf*8 + R)*KSTR + ks*8 + t2];
                mma8(s[nf], qa[ks], bp.x, bp.y);
            }
        }

        __syncwarp();
        if (it + 1 < 32) load_al(j0 + 64);

        unsigned nlo = 0, nhi = 0;
        if (it + 1 < 32){
            nlo = __ballot_sync(0xffffffffu, pm[j0 + 64 + lane] != 0);
            nhi = __ballot_sync(0xffffffffu, pm[j0 + 96 + lane] != 0);
        }

        // padding mask (S cols map to keys identically)
        #pragma unroll
        for (int nf = 0; nf < 8; nf++){
            int c = nf*8 + t2;
            unsigned bit0 = ((c   < 32) ? (mlo >> c)      : (mhi >> (c-32)))   & 1u;
            unsigned bit1 = ((c+1 < 32) ? (mlo >> (c+1))  : (mhi >> (c+1-32))) & 1u;
            if (bit0){ s[nf][0] = NEG_INF; s[nf][2] = NEG_INF; }
            if (bit1){ s[nf][1] = NEG_INF; s[nf][3] = NEG_INF; }
        }

        // online softmax in log2 domain
        float mx0 = -INFINITY, mx1 = -INFINITY;
        #pragma unroll
        for (int nf = 0; nf < 8; nf++){
            mx0 = fmaxf(mx0, fmaxf(s[nf][0], s[nf][1]));
            mx1 = fmaxf(mx1, fmaxf(s[nf][2], s[nf][3]));
        }
        mx0 = fmaxf(mx0, __shfl_xor_sync(0xffffffffu, mx0, 1));
        mx0 = fmaxf(mx0, __shfl_xor_sync(0xffffffffu, mx0, 2));
        mx1 = fmaxf(mx1, __shfl_xor_sync(0xffffffffu, mx1, 1));
        mx1 = fmaxf(mx1, __shfl_xor_sync(0xffffffffu, mx1, 2));
        float mn0 = fmaxf(mrun0, mx0);
        float mn1 = fmaxf(mrun1, mx1);
        float al0 = ex2(mrun0 - mn0);
        float al1 = ex2(mrun1 - mn1);
        mrun0 = mn0; mrun1 = mn1;

        float ls0 = 0.f, ls1 = 0.f;
        #pragma unroll
        for (int nf = 0; nf < 8; nf++){
            s[nf][0] = ex2(s[nf][0] - mn0); ls0 += s[nf][0];
            s[nf][1] = ex2(s[nf][1] - mn0); ls0 += s[nf][1];
            s[nf][2] = ex2(s[nf][2] - mn1); ls1 += s[nf][2];
            s[nf][3] = ex2(s[nf][3] - mn1); ls1 += s[nf][3];
            o[nf][0] *= al0; o[nf][1] *= al0; o[nf][2] *= al1; o[nf][3] *= al1;
        }
        ls0 += __shfl_xor_sync(0xffffffffu, ls0, 1);
        ls0 += __shfl_xor_sync(0xffffffffu, ls0, 2);
        ls1 += __shfl_xor_sync(0xffffffffu, ls1, 1);
        ls1 += __shfl_xor_sync(0xffffffffu, ls1, 2);
        l0 = l0*al0 + ls0;
        l1 = l1*al1 + ls1;

        // O += P @ V : S fragment used directly as A (mu-bijection absorbed by
        // loading V^T at key positions (2t, 2t+1)). Zero shuffles.
        #pragma unroll
        for (int ks = 0; ks < 8; ks++){
            float pa[4];
            pa[0] = to_tf32(s[ks][0]);
            pa[1] = to_tf32(s[ks][2]);
            pa[2] = to_tf32(s[ks][1]);
            pa[3] = to_tf32(s[ks][3]);
            #pragma unroll
            for (int nf = 0; nf < 8; nf++){
                float2 bp = *(const float2*)&Vs[(nf*8 + R)*KSTR + ks*8 + t2];
                mma8(o[nf], pa, bp.x, bp.y);
            }
        }
        __syncthreads();
        if (it + 2 < 32) load_kv((it+2) << 6, it & 1);
        mlo = nlo; mhi = nhi;
    }

    // epilogue: normalized O -> g_att as tf32, column-permuted
    const float inv0 = 1.0f / l0;
    const float inv1 = 1.0f / l1;
    float* orow0 = g_att + ((size_t)(b*N_ + r0))*C_;
    float* orow1 = orow0 + (size_t)8*C_;
    #pragma unroll
    for (int nf = 0; nf < 8; nf++){
        int c = h*64 + nf*8 + t2;
        orow0[perm8(c)]   = to_tf32(o[nf][0]*inv0);
        orow0[perm8(c+1)] = to_tf32(o[nf][1]*inv0);
        orow1[perm8(c)]   = to_tf32(o[nf][2]*inv1);
        orow1[perm8(c+1)] = to_tf32(o[nf][3]*inv1);
    }
}

// ---------------------------------------------------------------------------
extern "C" void kernel_launch(void* const* d_in, const int* in_sizes, int n_in,
                              void* d_out, int out_size)
{
    (void)in_sizes; (void)n_in; (void)out_size;
    const float* x      = (const float*)d_in[0];
    const int*   pmask  = (const int*)d_in[1];
    const float* alibi  = (const float*)d_in[2];
    const float* qkv_w  = (const float*)d_in[3];
    const float* qkv_b  = (const float*)d_in[4];
    const float* proj_w = (const float*)d_in[5];
    const float* proj_b = (const float*)d_in[6];
    float*       out    = (float*)d_out;

    const int GEMM_SMEM = (2*ABUF + 2*BBUF) * 4;              // 71680 B
    const int ATTN_SMEM = (4*KV_BUF + 128*ASTR) * 4;          // 110592 B
    cudaFuncSetAttribute(gemm_tf32_kernel, cudaFuncAttributeMaxDynamicSharedMemorySize, GEMM_SMEM);
    cudaFuncSetAttribute(attn_kernel, cudaFuncAttributeMaxDynamicSharedMemorySize, ATTN_SMEM);

    float *att_ptr = nullptr, *xc_ptr = nullptr, *wqkvT_ptr = nullptr, *wprojT_ptr = nullptr;
    cudaGetSymbolAddress((void**)&att_ptr,    g_att);
    cudaGetSymbolAddress((void**)&xc_ptr,     g_xc);
    cudaGetSymbolAddress((void**)&wqkvT_ptr,  g_wqkvT);
    cudaGetSymbolAddress((void**)&wprojT_ptr, g_wprojT);

    // 0) one-time conversions: tf32 + contraction-dim permutation
    {
        int n8 = (B_*N_*C_) / 8;
        cvt_perm_rows<<<(n8 + 255)/256, 256>>>(x, xc_ptr, n8);
        int nq = C_ * 3*C_;
        cvt_perm_T<<<(nq + 255)/256, 256>>>(qkv_w, wqkvT_ptr, C_, 3*C_);
        int np = C_ * C_;
        cvt_perm_T<<<(np + 255)/256, 256>>>(proj_w, wprojT_ptr, C_, C_);
    }
    // 1) QKV projection + bias + scatter (q,k d-perm; v transposed, unpermuted)
    gemm_tf32_kernel<<<dim3(2304/96, 8192/128), 128, GEMM_SMEM>>>(
        xc_ptr, wqkvT_ptr, qkv_b, nullptr, 8192, 768, 2304, 1);
    // 2) fused attention -> g_att (tf32, c-permuted)
    attn_kernel<<<dim3(N_/128, H_, B_), 256, ATTN_SMEM>>>(alibi, pmask);
    // 3) output projection + bias -> d_out (fp32)
    gemm_tf32_kernel<<<dim3(768/96, 8192/128), 128, GEMM_SMEM>>>(
        att_ptr, wprojT_ptr, proj_b, out, 8192, 768, 768, 0);
}

// round 14
// speedup vs baseline: 1.0276x; 1.0276x over previous
#include <cuda_runtime.h>
#include <cstdint>

// Problem constants
#define B_  4
#define H_  12
#define N_  2048
#define D_  64
#define C_  768
#define BHND (B_*H_*N_*D_)

// Scratch (device globals — no allocation allowed)
__device__ float g_q[BHND];            // [b,h][n][d]  tf32, d-permuted
__device__ float g_k[BHND];            // [b,h][j][d]  tf32, d-permuted, KEY-COMPACTED rows
__device__ float g_v[BHND];            // [b,h][d][j]  tf32, transposed, KEY-COMPACTED cols
__device__ float g_att[B_*N_*C_];      // [b,n][c]     tf32, c-permuted
__device__ float g_xc[B_*N_*C_];       // x, tf32, k-permuted
__device__ float g_wqkvT[3*C_*C_];     // qkv_w transposed [2304][768], tf32, k-permuted
__device__ float g_wprojT[C_*C_];      // proj_w transposed [768][768], tf32, k-permuted
__device__ int   g_pos[B_*N_];         // original key n -> compacted slot
__device__ int   g_idx[B_*N_];         // compacted slot -> original key n
__device__ int   g_valid[B_];          // surviving (unmasked) keys per batch

#define LOG2E 1.4426950408889634f

__device__ __forceinline__ float to_tf32(float x){
    uint32_t u = __float_as_uint(x);
    asm("cvt.rna.tf32.f32 %0, %0;" : "+r"(u));
    return __uint_as_float(u);
}
__device__ __forceinline__ float ex2(float x){
    float r;
    asm("ex2.approx.ftz.f32 %0, %1;" : "=f"(r) : "f"(x));
    return r;
}
__device__ __forceinline__ int perm8(int j){ return (j & ~7) + 2*(j&3) + ((j>>2)&1); }

__device__ __forceinline__ void cp_async16(float* smem_dst, const float* gsrc){
    uint32_t s = (uint32_t)__cvta_generic_to_shared(smem_dst);
    asm volatile("cp.async.cg.shared.global [%0], [%1], 16;\n" :: "r"(s), "l"(gsrc));
}
__device__ __forceinline__ void cp_async4(float* smem_dst, const float* gsrc){
    uint32_t s = (uint32_t)__cvta_generic_to_shared(smem_dst);
    asm volatile("cp.async.ca.shared.global [%0], [%1], 4;\n" :: "r"(s), "l"(gsrc));
}
__device__ __forceinline__ void cp_commit(){ asm volatile("cp.async.commit_group;\n"); }
template<int NN>
__device__ __forceinline__ void cp_wait(){ asm volatile("cp.async.wait_group %0;\n" :: "n"(NN)); }

// D = A(16x8, row) * B(8x8, col) + D ; tf32 inputs, fp32 accum
__device__ __forceinline__ void mma8(float d[4], const float a[4], float b0, float b1){
    asm volatile(
        "mma.sync.aligned.m16n8k8.row.col.f32.tf32.tf32.f32 "
        "{%0,%1,%2,%3},{%4,%5,%6,%7},{%8,%9},{%0,%1,%2,%3};\n"
        : "+f"(d[0]), "+f"(d[1]), "+f"(d[2]), "+f"(d[3])
        : "r"(__float_as_uint(a[0])), "r"(__float_as_uint(a[1])),
          "r"(__float_as_uint(a[2])), "r"(__float_as_uint(a[3])),
          "r"(__float_as_uint(b0)),   "r"(__float_as_uint(b1)));
}

// ---------------------------------------------------------------------------
// One-time kernels
// ---------------------------------------------------------------------------
__global__ void cvt_perm_rows(const float* __restrict__ in, float* __restrict__ out, int n8){
    int g = blockIdx.x*blockDim.x + threadIdx.x;
    if (g >= n8) return;
    const float4* p = (const float4*)(in + (size_t)g*8);
    float4 u = p[0], v = p[1];
    float vals[8] = {u.x,u.y,u.z,u.w,v.x,v.y,v.z,v.w};
    float* o = out + (size_t)g*8;
    #pragma unroll
    for (int j = 0; j < 8; j++) o[2*(j&3)+((j>>2)&1)] = to_tf32(vals[j]);
}
__global__ void cvt_perm_T(const float* __restrict__ w, float* __restrict__ wt, int K, int NO){
    int idx = blockIdx.x*blockDim.x + threadIdx.x;
    if (idx >= K*NO) return;
    int k = idx / NO, n = idx % NO;
    wt[(size_t)n*K + perm8(k)] = to_tf32(w[idx]);
}

// Stable partition of keys: survivors (mask==0) first. One block per batch.
__global__ void build_index(const int* __restrict__ pmask){
    __shared__ int sc[256];
    int b = blockIdx.x, tid = threadIdx.x;
    const int* pm = pmask + b*N_;
    int m[8]; int c = 0;
    #pragma unroll
    for (int j = 0; j < 8; j++){ m[j] = (pm[tid*8 + j] == 0); c += m[j]; }
    sc[tid] = c;
    __syncthreads();
    // Hillis-Steele inclusive scan over 256 counts
    for (int off = 1; off < 256; off <<= 1){
        int v = sc[tid];
        int u = (tid >= off) ? sc[tid - off] : 0;
        __syncthreads();
        sc[tid] = v + u;
        __syncthreads();
    }
    int excl  = sc[tid] - c;
    int valid = sc[255];
    if (tid == 0) g_valid[b] = valid;
    int sp = excl;                 // survivors before my chunk
    int mp = tid*8 - excl;         // masked before my chunk
    #pragma unroll
    for (int j = 0; j < 8; j++){
        int n = tid*8 + j;
        int p;
        if (m[j]) { p = sp++; }
        else      { p = valid + mp++; }
        g_pos[b*N_ + n] = p;
        g_idx[b*N_ + p] = n;
    }
}

// ---------------------------------------------------------------------------
// TF32 GEMM:  out = A[M,K] @ Wt[N,K]^T + bias   (A, Wt pre-tf32, k-permuted)
// CTA tile 128x96, 128 threads, 4 warps (2x2), warp tile 64x48, occ 3.
// mode 0: row-major fp32 store; mode 1: QKV scatter (k/v key-compacted)
// ---------------------------------------------------------------------------
#define GSTR 40
#define ABUF (128*GSTR)
#define BBUF (96*GSTR)

__global__ __launch_bounds__(128,3) void gemm_tf32_kernel(
    const float* __restrict__ A, const float* __restrict__ Wt,
    const float* __restrict__ bias, float* __restrict__ out,
    int M, int K, int NO, int mode)
{
    extern __shared__ float smem[];
    float* sA = smem;                 // [2][128*40]
    float* sB = smem + 2*ABUF;        // [2][96*40]

    const int tid  = threadIdx.x;
    const int lane = tid & 31;
    const int warp = tid >> 5;
    const int wm   = warp & 1;
    const int wn   = warp >> 1;
    const int m0   = blockIdx.y * 128;
    const int n0   = blockIdx.x * 96;
    const int R    = lane >> 2;
    const int t2   = (lane & 3) << 1;

    float acc[4][6][4];
    #pragma unroll
    for (int i = 0; i < 4; i++)
        #pragma unroll
        for (int j = 0; j < 6; j++)
            #pragma unroll
            for (int r = 0; r < 4; r++) acc[i][j][r] = 0.f;

    const int steps = K >> 5;

    auto load_step = [&](int k0, int buf){
        float* dA = sA + buf*ABUF;
        float* dB = sB + buf*BBUF;
        #pragma unroll
        for (int i = 0; i < 8; i++){
            int id  = tid + i*128;
            int row = id >> 3;
            int c4  = (id & 7) << 2;
            cp_async16(&dA[row*GSTR + c4], A  + (size_t)(m0 + row)*K + k0 + c4);
        }
        #pragma unroll
        for (int i = 0; i < 6; i++){
            int id  = tid + i*128;
            int row = id >> 3;
            int c4  = (id & 7) << 2;
            cp_async16(&dB[row*GSTR + c4], Wt + (size_t)(n0 + row)*K + k0 + c4);
        }
        cp_commit();
    };

    load_step(0, 0);
    load_step(32, 1);

    for (int it = 0; it < steps; it++){
        if (it + 1 < steps) cp_wait<1>(); else cp_wait<0>();
        __syncthreads();

        const float* cA = sA + (it & 1)*ABUF;
        const float* cB = sB + (it & 1)*BBUF;

        #pragma unroll
        for (int kk = 0; kk < 4; kk++){
            float af[4][4];
            #pragma unroll
            for (int mf = 0; mf < 4; mf++){
                int rbase = wm*64 + mf*16 + R;
                float2 p0 = *(const float2*)&cA[rbase*GSTR + kk*8 + t2];
                float2 p1 = *(const float2*)&cA[(rbase+8)*GSTR + kk*8 + t2];
                af[mf][0] = p0.x; af[mf][1] = p1.x; af[mf][2] = p0.y; af[mf][3] = p1.y;
            }
            #pragma unroll
            for (int nf = 0; nf < 6; nf++){
                float2 bp = *(const float2*)&cB[(wn*48 + nf*8 + R)*GSTR + kk*8 + t2];
                #pragma unroll
                for (int mf = 0; mf < 4; mf++)
                    mma8(acc[mf][nf], af[mf], bp.x, bp.y);
            }
        }
        __syncthreads();
        if (it + 2 < steps) load_step((it+2) << 5, it & 1);
    }

    // epilogue
    #pragma unroll
    for (int mf = 0; mf < 4; mf++){
        #pragma unroll
        for (int nf = 0; nf < 6; nf++){
            #pragma unroll
            for (int rr = 0; rr < 2; rr++){
                int gm  = m0 + wm*64 + mf*16 + R + rr*8;
                int gn0 = n0 + wn*48 + nf*8 + t2;
                float v0 = acc[mf][nf][rr*2+0] + bias[gn0];
                float v1 = acc[mf][nf][rr*2+1] + bias[gn0+1];
                if (mode == 0){
                    *(float2*)(out + (size_t)gm*NO + gn0) = make_float2(v0, v1);
                } else {
                    int three = gn0 / 768;
                    int rem   = gn0 % 768;
                    int h     = rem / 64;
                    int d     = rem & 63;
                    int b     = gm >> 11;
                    int n     = gm & 2047;
                    size_t bh = (size_t)(b*H_ + h);
                    if (three == 0){
                        size_t ro = (bh*N_ + n)*D_;
                        g_q[ro + perm8(d)]   = to_tf32(v0);
                        g_q[ro + perm8(d+1)] = to_tf32(v1);
                    } else if (three == 1){
                        int nc = g_pos[b*N_ + n];          // compacted key row
                        size_t ro = (bh*N_ + nc)*D_;
                        g_k[ro + perm8(d)]   = to_tf32(v0);
                        g_k[ro + perm8(d+1)] = to_tf32(v1);
                    } else {  // v: transposed [d][j], compacted column
                        int nc = g_pos[b*N_ + n];
                        size_t vo = (bh*D_ + d)*N_ + nc;
                        g_v[vo]      = to_tf32(v0);
                        g_v[vo + N_] = to_tf32(v1);
                    }
                }
            }
        }
    }
}

// ---------------------------------------------------------------------------
// Fused attention over COMPACTED keys: 128 q-rows/CTA, 8 warps x 16 rows,
// key tile 64, ntiles = ceil(valid/64) (~17 avg instead of 32).
// Alibi gathered per-element via idx (cp.async 4B); tail cols -> -inf.
// PV consumes the S fragment directly (mu-bijection absorbed by V^T layout).
// ---------------------------------------------------------------------------
#define KSTR 72
#define KV_BUF (64*KSTR)
#define ASTR 72
#define NEG_INF __int_as_float(0xff800000)

__global__ __launch_bounds__(256,2) void attn_kernel(const float* __restrict__ alibi)
{
    extern __shared__ float sm[];
    float* KsB = sm;                   // [2][64*72]
    float* VsB = sm + 2*KV_BUF;        // [2][64*72]
    float* ALs = sm + 4*KV_BUF;        // [128*72] alibi stage (warp-private rows)

    const int tid  = threadIdx.x;
    const int lane = tid & 31;
    const int warp = tid >> 5;
    const int q0 = blockIdx.x * 128;
    const int h  = blockIdx.y;
    const int b  = blockIdx.z;
    const int R  = lane >> 2;
    const int t2 = (lane & 3) << 1;

    const int valid  = g_valid[b];
    const int ntiles = (valid + 63) >> 6;

    const int r0 = q0 + warp*16 + R;
    const size_t bh = (size_t)(b*H_ + h);
    const float* qp = g_q + bh*N_*D_;

    const float qscale = 0.125f * LOG2E;
    float qa[8][4];
    #pragma unroll
    for (int ks = 0; ks < 8; ks++){
        float2 p0 = *(const float2*)&qp[(size_t)r0*64 + ks*8 + t2];
        float2 p1 = *(const float2*)&qp[(size_t)(r0+8)*64 + ks*8 + t2];
        qa[ks][0] = to_tf32(p0.x*qscale); qa[ks][1] = to_tf32(p1.x*qscale);
        qa[ks][2] = to_tf32(p0.y*qscale); qa[ks][3] = to_tf32(p1.y*qscale);
    }

    float o[8][4];
    #pragma unroll
    for (int nf = 0; nf < 8; nf++){ o[nf][0]=o[nf][1]=o[nf][2]=o[nf][3]=0.f; }
    float mrun0 = -1e30f, mrun1 = -1e30f, l0 = 0.f, l1 = 0.f;

    const float* kbase = g_k + bh*N_*D_;            // compacted [j][d]
    const float* vbase = g_v + bh*(size_t)D_*N_;    // compacted [d][j]
    const float* abase = alibi + (bh*N_ + q0 + warp*16)*(size_t)N_;
    const int*   ibase = g_idx + b*N_;

    auto load_kv = [&](int j0, int buf){
        float* dK = KsB + buf*KV_BUF;
        float* dV = VsB + buf*KV_BUF;
        #pragma unroll
        for (int i = 0; i < 4; i++){
            int id  = tid + i*256;
            int row = id >> 4;
            int c4  = (id & 15) << 2;
            cp_async16(&dK[row*KSTR + c4], kbase + (size_t)(j0+row)*64 + c4);
            cp_async16(&dV[row*KSTR + c4], vbase + (size_t)row*N_ + j0 + c4);
        }
        cp_commit();
    };
    // gathered alibi: warp-private 16 rows x 64 compacted cols
    auto load_al = [&](int j0){
        int ix0 = ibase[j0 + lane];
        int ix1 = ibase[j0 + 32 + lane];
        #pragma unroll
        for (int i = 0; i < 32; i++){
            int rr = i >> 1;
            int cc = ((i & 1) << 5) + lane;
            int ix = (i & 1) ? ix1 : ix0;
            cp_async4(&ALs[(warp*16 + rr)*ASTR + cc], abase + (size_t)rr*N_ + ix);
        }
        cp_commit();
    };

    load_kv(0, 0);
    if (ntiles > 1) load_kv(64, 1); else cp_commit();  // keep group count invariant
    load_al(0);

    for (int it = 0; it < ntiles; it++){
        const int j0 = it << 6;
        if (it == 0 || it == ntiles-1) cp_wait<0>(); else cp_wait<1>();
        __syncthreads();

        const float* Ks = KsB + (it & 1)*KV_BUF;
        const float* Vs = VsB + (it & 1)*KV_BUF;

        // S init = alibi * log2e (gathered stage)
        float s[8][4];
        #pragma unroll
        for (int nf = 0; nf < 8; nf++){
            int c = nf*8 + t2;
            float2 a0 = *(const float2*)&ALs[(warp*16 + R)*ASTR + c];
            float2 a1 = *(const float2*)&ALs[(warp*16 + R + 8)*ASTR + c];
            s[nf][0] = a0.x*LOG2E; s[nf][1] = a0.y*LOG2E;
            s[nf][2] = a1.x*LOG2E; s[nf][3] = a1.y*LOG2E;
        }

        // S += Q' @ K^T
        #pragma unroll
        for (int ks = 0; ks < 8; ks++){
            #pragma unroll
            for (int nf = 0; nf < 8; nf++){
                float2 bp = *(const float2*)&Ks[(nf*8 + R)*KSTR + ks*8 + t2];
                mma8(s[nf], qa[ks], bp.x, bp.y);
            }
        }

        __syncwarp();
        if (it + 1 < ntiles) load_al(j0 + 64);

        // tail mask: columns beyond valid
        int rem = valid - j0;
        if (rem < 64){
            #pragma unroll
            for (int nf = 0; nf < 8; nf++){
                int c = nf*8 + t2;
                if (c   >= rem){ s[nf][0] = NEG_INF; s[nf][2] = NEG_INF; }
                if (c+1 >= rem){ s[nf][1] = NEG_INF; s[nf][3] = NEG_INF; }
            }
        }

        // online softmax in log2 domain
        float mx0 = -INFINITY, mx1 = -INFINITY;
        #pragma unroll
        for (int nf = 0; nf < 8; nf++){
            mx0 = fmaxf(mx0, fmaxf(s[nf][0], s[nf][1]));
            mx1 = fmaxf(mx1, fmaxf(s[nf][2], s[nf][3]));
        }
        mx0 = fmaxf(mx0, __shfl_xor_sync(0xffffffffu, mx0, 1));
        mx0 = fmaxf(mx0, __shfl_xor_sync(0xffffffffu, mx0, 2));
        mx1 = fmaxf(mx1, __shfl_xor_sync(0xffffffffu, mx1, 1));
        mx1 = fmaxf(mx1, __shfl_xor_sync(0xffffffffu, mx1, 2));
        float mn0 = fmaxf(mrun0, mx0);
        float mn1 = fmaxf(mrun1, mx1);
        float al0 = ex2(mrun0 - mn0);
        float al1 = ex2(mrun1 - mn1);
        mrun0 = mn0; mrun1 = mn1;

        float ls0 = 0.f, ls1 = 0.f;
        #pragma unroll
        for (int nf = 0; nf < 8; nf++){
            s[nf][0] = ex2(s[nf][0] - mn0); ls0 += s[nf][0];
            s[nf][1] = ex2(s[nf][1] - mn0); ls0 += s[nf][1];
            s[nf][2] = ex2(s[nf][2] - mn1); ls1 += s[nf][2];
            s[nf][3] = ex2(s[nf][3] - mn1); ls1 += s[nf][3];
            o[nf][0] *= al0; o[nf][1] *= al0; o[nf][2] *= al1; o[nf][3] *= al1;
        }
        ls0 += __shfl_xor_sync(0xffffffffu, ls0, 1);
        ls0 += __shfl_xor_sync(0xffffffffu, ls0, 2);
        ls1 += __shfl_xor_sync(0xffffffffu, ls1, 1);
        ls1 += __shfl_xor_sync(0xffffffffu, ls1, 2);
        l0 = l0*al0 + ls0;
        l1 = l1*al1 + ls1;

        // O += P @ V (S fragment direct as A; V^T supplies mu-permuted keys)
        #pragma unroll
        for (int ks = 0; ks < 8; ks++){
            float pa[4];
            pa[0] = to_tf32(s[ks][0]);
            pa[1] = to_tf32(s[ks][2]);
            pa[2] = to_tf32(s[ks][1]);
            pa[3] = to_tf32(s[ks][3]);
            #pragma unroll
            for (int nf = 0; nf < 8; nf++){
                float2 bp = *(const float2*)&Vs[(nf*8 + R)*KSTR + ks*8 + t2];
                mma8(o[nf], pa, bp.x, bp.y);
            }
        }
        __syncthreads();
        if (it + 2 < ntiles) load_kv((it+2) << 6, it & 1);
    }

    // epilogue: normalized O -> g_att as tf32, column-permuted
    const float inv0 = 1.0f / l0;
    const float inv1 = 1.0f / l1;
    float* orow0 = g_att + ((size_t)(b*N_ + r0))*C_;
    float* orow1 = orow0 + (size_t)8*C_;
    #pragma unroll
    for (int nf = 0; nf < 8; nf++){
        int c = h*64 + nf*8 + t2;
        orow0[perm8(c)]   = to_tf32(o[nf][0]*inv0);
        orow0[perm8(c+1)] = to_tf32(o[nf][1]*inv0);
        orow1[perm8(c)]   = to_tf32(o[nf][2]*inv1);
        orow1[perm8(c+1)] = to_tf32(o[nf][3]*inv1);
    }
}

// ---------------------------------------------------------------------------
extern "C" void kernel_launch(void* const* d_in, const int* in_sizes, int n_in,
                              void* d_out, int out_size)
{
    (void)in_sizes; (void)n_in; (void)out_size;
    const float* x      = (const float*)d_in[0];
    const int*   pmask  = (const int*)d_in[1];
    const float* alibi  = (const float*)d_in[2];
    const float* qkv_w  = (const float*)d_in[3];
    const float* qkv_b  = (const float*)d_in[4];
    const float* proj_w = (const float*)d_in[5];
    const float* proj_b = (const float*)d_in[6];
    float*       out    = (float*)d_out;

    const int GEMM_SMEM = (2*ABUF + 2*BBUF) * 4;              // 71680 B
    const int ATTN_SMEM = (4*KV_BUF + 128*ASTR) * 4;          // 110592 B
    cudaFuncSetAttribute(gemm_tf32_kernel, cudaFuncAttributeMaxDynamicSharedMemorySize, GEMM_SMEM);
    cudaFuncSetAttribute(attn_kernel, cudaFuncAttributeMaxDynamicSharedMemorySize, ATTN_SMEM);

    float *att_ptr = nullptr, *xc_ptr = nullptr, *wqkvT_ptr = nullptr, *wprojT_ptr = nullptr;
    cudaGetSymbolAddress((void**)&att_ptr,    g_att);
    cudaGetSymbolAddress((void**)&xc_ptr,     g_xc);
    cudaGetSymbolAddress((void**)&wqkvT_ptr,  g_wqkvT);
    cudaGetSymbolAddress((void**)&wprojT_ptr, g_wprojT);

    // 0) one-time: mask scan + tf32/permute conversions
    build_index<<<B_, 256>>>(pmask);
    {
        int n8 = (B_*N_*C_) / 8;
        cvt_perm_rows<<<(n8 + 255)/256, 256>>>(x, xc_ptr, n8);
        int nq = C_ * 3*C_;
        cvt_perm_T<<<(nq + 255)/256, 256>>>(qkv_w, wqkvT_ptr, C_, 3*C_);
        int np = C_ * C_;
        cvt_perm_T<<<(np + 255)/256, 256>>>(proj_w, wprojT_ptr, C_, C_);
    }
    // 1) QKV projection + bias + scatter (k/v key-compacted)
    gemm_tf32_kernel<<<dim3(2304/96, 8192/128), 128, GEMM_SMEM>>>(
        xc_ptr, wqkvT_ptr, qkv_b, nullptr, 8192, 768, 2304, 1);
    // 2) fused attention over compacted keys -> g_att (tf32, c-permuted)
    attn_kernel<<<dim3(N_/128, H_, B_), 256, ATTN_SMEM>>>(alibi);
    // 3) output projection + bias -> d_out (fp32)
    gemm_tf32_kernel<<<dim3(768/96, 8192/128), 128, GEMM_SMEM>>>(
        att_ptr, wprojT_ptr, proj_b, out, 8192, 768, 768, 0);
}

// round 16
// speedup vs baseline: 1.2252x; 1.1923x over previous
#include <cuda_runtime.h>
#include <cstdint>

// Problem constants
#define B_  4
#define H_  12
#define N_  2048
#define D_  64
#define C_  768
#define BHND (B_*H_*N_*D_)

// Scratch (device globals — no allocation allowed)
__device__ float g_q[BHND];            // [b,h][n][d]  tf32, d-permuted
__device__ float g_k[BHND];            // [b,h][j][d]  tf32, d-permuted, KEY-COMPACTED rows
__device__ float g_v[BHND];            // [b,h][d][j]  tf32, transposed, KEY-COMPACTED cols
__device__ float g_att[B_*N_*C_];      // [b,n][c]     tf32, c-permuted
__device__ float g_xc[B_*N_*C_];       // x, tf32, k-permuted
__device__ float g_wqkvT[3*C_*C_];     // qkv_w transposed [2304][768], tf32, k-permuted
__device__ float g_wprojT[C_*C_];      // proj_w transposed [768][768], tf32, k-permuted
__device__ int   g_idx[B_*N_];         // compacted slot -> original key n
__device__ int   g_valid[B_];          // surviving (unmasked) keys per batch

#define LOG2E 1.4426950408889634f

__device__ __forceinline__ float to_tf32(float x){
    uint32_t u = __float_as_uint(x);
    asm("cvt.rna.tf32.f32 %0, %0;" : "+r"(u));
    return __uint_as_float(u);
}
__device__ __forceinline__ float ex2(float x){
    float r;
    asm("ex2.approx.ftz.f32 %0, %1;" : "=f"(r) : "f"(x));
    return r;
}
__device__ __forceinline__ int perm8(int j){ return (j & ~7) + 2*(j&3) + ((j>>2)&1); }

__device__ __forceinline__ void cp_async16(void* smem_dst, const void* gsrc){
    uint32_t s = (uint32_t)__cvta_generic_to_shared(smem_dst);
    asm volatile("cp.async.cg.shared.global [%0], [%1], 16;\n" :: "r"(s), "l"(gsrc));
}
__device__ __forceinline__ void cp_commit(){ asm volatile("cp.async.commit_group;\n"); }
template<int NN>
__device__ __forceinline__ void cp_wait(){ asm volatile("cp.async.wait_group %0;\n" :: "n"(NN)); }

// D = A(16x8, row) * B(8x8, col) + D ; tf32 inputs, fp32 accum
__device__ __forceinline__ void mma8(float d[4], const float a[4], float b0, float b1){
    asm volatile(
        "mma.sync.aligned.m16n8k8.row.col.f32.tf32.tf32.f32 "
        "{%0,%1,%2,%3},{%4,%5,%6,%7},{%8,%9},{%0,%1,%2,%3};\n"
        : "+f"(d[0]), "+f"(d[1]), "+f"(d[2]), "+f"(d[3])
        : "r"(__float_as_uint(a[0])), "r"(__float_as_uint(a[1])),
          "r"(__float_as_uint(a[2])), "r"(__float_as_uint(a[3])),
          "r"(__float_as_uint(b0)),   "r"(__float_as_uint(b1)));
}

// ---------------------------------------------------------------------------
// One-time kernels
// ---------------------------------------------------------------------------
__global__ void cvt_perm_rows(const float* __restrict__ in, float* __restrict__ out, int n8){
    int g = blockIdx.x*blockDim.x + threadIdx.x;
    if (g >= n8) return;
    const float4* p = (const float4*)(in + (size_t)g*8);
    float4 u = p[0], v = p[1];
    float vals[8] = {u.x,u.y,u.z,u.w,v.x,v.y,v.z,v.w};
    float* o = out + (size_t)g*8;
    #pragma unroll
    for (int j = 0; j < 8; j++) o[2*(j&3)+((j>>2)&1)] = to_tf32(vals[j]);
}
__global__ void cvt_perm_T(const float* __restrict__ w, float* __restrict__ wt, int K, int NO){
    int idx = blockIdx.x*blockDim.x + threadIdx.x;
    if (idx >= K*NO) return;
    int k = idx / NO, n = idx % NO;
    wt[(size_t)n*K + perm8(k)] = to_tf32(w[idx]);
}
// Stable partition of keys: survivors (mask==0) first. One block per batch.
__global__ void build_index(const int* __restrict__ pmask){
    __shared__ int sc[256];
    int b = blockIdx.x, tid = threadIdx.x;
    const int* pm = pmask + b*N_;
    int m[8]; int c = 0;
    #pragma unroll
    for (int j = 0; j < 8; j++){ m[j] = (pm[tid*8 + j] == 0); c += m[j]; }
    sc[tid] = c;
    __syncthreads();
    for (int off = 1; off < 256; off <<= 1){
        int v = sc[tid];
        int u = (tid >= off) ? sc[tid - off] : 0;
        __syncthreads();
        sc[tid] = v + u;
        __syncthreads();
    }
    int excl  = sc[tid] - c;
    int valid = sc[255];
    if (tid == 0) g_valid[b] = valid;
    int sp = excl, mp = tid*8 - excl;
    #pragma unroll
    for (int j = 0; j < 8; j++){
        int n = tid*8 + j;
        int p;
        if (m[j]) { p = sp++; } else { p = valid + mp++; }
        g_idx[b*N_ + p] = n;
    }
}

// ---------------------------------------------------------------------------
// TF32 GEMM:  out = A[M,K] @ Wt[N,K]^T + bias   (A, Wt pre-tf32, k-permuted)
// CTA tile 128x96, 128 threads, 4 warps (2x2), warp tile 64x48, occ 3.
// mode 0: row-major fp32 store (proj)
// mode 1: Q scatter  (cols 0..767  -> g_q, d-permuted tf32)
// mode 2: KV GEMM over COMPACTED survivor rows (A gathered via g_idx),
//         cols 0..1535 -> g_k (d-perm) / g_v (transposed); early-exit tiles.
// ---------------------------------------------------------------------------
#define GSTR 40
#define ABUF (128*GSTR)
#define BBUF (96*GSTR)

__global__ __launch_bounds__(128,3) void gemm_tf32_kernel(
    const float* __restrict__ A, const float* __restrict__ Wt,
    const float* __restrict__ bias, float* __restrict__ out,
    int M, int K, int NO, int mode)
{
    extern __shared__ float smem[];
    float* sA = smem;                 // [2][128*40]
    float* sB = smem + 2*ABUF;        // [2][96*40]

    const int tid  = threadIdx.x;
    const int lane = tid & 31;
    const int warp = tid >> 5;
    const int wm   = warp & 1;
    const int wn   = warp >> 1;
    const int n0   = blockIdx.x * 96;
    const int R    = lane >> 2;
    const int t2   = (lane & 3) << 1;

    // row-tile resolution
    int bt = 0, j0 = 0, valid = 0, m0 = 0;
    if (mode == 2){
        bt = blockIdx.y >> 4;            // batch
        j0 = (blockIdx.y & 15) * 128;    // compacted row-tile start
        valid = g_valid[bt];
        if (j0 >= valid) return;         // fully masked tile -> nothing to do
    } else {
        m0 = blockIdx.y * 128;
    }

    // per-thread A row pointers for the loader (8 slots, constant across chunks)
    const float* aptr[8];
    {
        #pragma unroll
        for (int i = 0; i < 8; i++){
            int id  = tid + i*128;
            int row = id >> 3;
            int c4  = (id & 7) << 2;
            if (mode == 2){
                int j = j0 + row; if (j > valid-1) j = valid-1;
                int orig = g_idx[bt*N_ + j];
                aptr[i] = A + ((size_t)bt*N_ + orig)*K + c4;
            } else {
                aptr[i] = A + (size_t)(m0 + row)*K + c4;
            }
        }
    }

    float acc[4][6][4];
    #pragma unroll
    for (int i = 0; i < 4; i++)
        #pragma unroll
        for (int j = 0; j < 6; j++)
            #pragma unroll
            for (int r = 0; r < 4; r++) acc[i][j][r] = 0.f;

    const int steps = K >> 5;

    auto load_step = [&](int k0, int buf){
        float* dA = sA + buf*ABUF;
        float* dB = sB + buf*BBUF;
        #pragma unroll
        for (int i = 0; i < 8; i++){
            int id  = tid + i*128;
            int row = id >> 3;
            int c4  = (id & 7) << 2;
            cp_async16(&dA[row*GSTR + c4], aptr[i] + k0);
        }
        #pragma unroll
        for (int i = 0; i < 6; i++){
            int id  = tid + i*128;
            int row = id >> 3;
            int c4  = (id & 7) << 2;
            cp_async16(&dB[row*GSTR + c4], Wt + (size_t)(n0 + row)*K + k0 + c4);
        }
        cp_commit();
    };

    load_step(0, 0);
    load_step(32, 1);

    for (int it = 0; it < steps; it++){
        if (it + 1 < steps) cp_wait<1>(); else cp_wait<0>();
        __syncthreads();

        const float* cA = sA + (it & 1)*ABUF;
        const float* cB = sB + (it & 1)*BBUF;

        #pragma unroll
        for (int kk = 0; kk < 4; kk++){
            float af[4][4];
            #pragma unroll
            for (int mf = 0; mf < 4; mf++){
                int rbase = wm*64 + mf*16 + R;
                float2 p0 = *(const float2*)&cA[rbase*GSTR + kk*8 + t2];
                float2 p1 = *(const float2*)&cA[(rbase+8)*GSTR + kk*8 + t2];
                af[mf][0] = p0.x; af[mf][1] = p1.x; af[mf][2] = p0.y; af[mf][3] = p1.y;
            }
            #pragma unroll
            for (int nf = 0; nf < 6; nf++){
                float2 bp = *(const float2*)&cB[(wn*48 + nf*8 + R)*GSTR + kk*8 + t2];
                #pragma unroll
                for (int mf = 0; mf < 4; mf++)
                    mma8(acc[mf][nf], af[mf], bp.x, bp.y);
            }
        }
        __syncthreads();
        if (it + 2 < steps) load_step((it+2) << 5, it & 1);
    }

    // epilogue
    #pragma unroll
    for (int mf = 0; mf < 4; mf++){
        #pragma unroll
        for (int nf = 0; nf < 6; nf++){
            #pragma unroll
            for (int rr = 0; rr < 2; rr++){
                int lrow = wm*64 + mf*16 + R + rr*8;
                int gn0  = n0 + wn*48 + nf*8 + t2;
                float v0 = acc[mf][nf][rr*2+0] + bias[gn0];
                float v1 = acc[mf][nf][rr*2+1] + bias[gn0+1];
                if (mode == 0){
                    int gm = m0 + lrow;
                    *(float2*)(out + (size_t)gm*NO + gn0) = make_float2(v0, v1);
                } else if (mode == 1){
                    int gm = m0 + lrow;
                    int h  = gn0 / 64;
                    int d  = gn0 & 63;
                    int b  = gm >> 11;
                    int n  = gm & 2047;
                    size_t ro = ((size_t)(b*H_ + h)*N_ + n)*D_;
                    g_q[ro + perm8(d)]   = to_tf32(v0);
                    g_q[ro + perm8(d+1)] = to_tf32(v1);
                } else {
                    int j = j0 + lrow;
                    if (j < valid){
                        int three = gn0 / 768;        // 0=k, 1=v
                        int rem   = gn0 % 768;
                        int h     = rem / 64;
                        int d     = rem & 63;
                        size_t bh = (size_t)(bt*H_ + h);
                        if (three == 0){
                            size_t ro = (bh*N_ + j)*D_;
                            g_k[ro + perm8(d)]   = to_tf32(v0);
                            g_k[ro + perm8(d+1)] = to_tf32(v1);
                        } else {
                            size_t vo = (bh*D_ + d)*N_ + j;
                            g_v[vo]      = to_tf32(v0);
                            g_v[vo + N_] = to_tf32(v1);
                        }
                    }
                }
            }
        }
    }
}

// ---------------------------------------------------------------------------
// Fused attention over COMPACTED keys: 128 q-rows/CTA, 8 warps x 16 rows,
// key tile 64, ntiles = ceil(valid/64). Alibi gathered straight into
// registers (idx int2 loads hidden under QK; scalar alibi LDGs after QK).
// PV consumes the S fragment directly (mu-bijection absorbed by V^T layout).
// ---------------------------------------------------------------------------
#define KSTR 72
#define KV_BUF (64*KSTR)
#define NEG_INF __int_as_float(0xff800000)

__global__ __launch_bounds__(256,2) void attn_kernel(const float* __restrict__ alibi)
{
    extern __shared__ float sm[];
    float* KsB = sm;                   // [2][64*72]
    float* VsB = sm + 2*KV_BUF;        // [2][64*72]

    const int tid  = threadIdx.x;
    const int lane = tid & 31;
    const int warp = tid >> 5;
    const int q0 = blockIdx.x * 128;
    const int h  = blockIdx.y;
    const int b  = blockIdx.z;
    const int R  = lane >> 2;
    const int t2 = (lane & 3) << 1;

    const int valid  = g_valid[b];
    const int ntiles = (valid + 63) >> 6;

    const int r0 = q0 + warp*16 + R;
    const size_t bh = (size_t)(b*H_ + h);
    const float* qp = g_q + bh*N_*D_;

    const float qscale = 0.125f * LOG2E;
    float qa[8][4];
    #pragma unroll
    for (int ks = 0; ks < 8; ks++){
        float2 p0 = *(const float2*)&qp[(size_t)r0*64 + ks*8 + t2];
        float2 p1 = *(const float2*)&qp[(size_t)(r0+8)*64 + ks*8 + t2];
        qa[ks][0] = to_tf32(p0.x*qscale); qa[ks][1] = to_tf32(p1.x*qscale);
        qa[ks][2] = to_tf32(p0.y*qscale); qa[ks][3] = to_tf32(p1.y*qscale);
    }

    float o[8][4];
    #pragma unroll
    for (int nf = 0; nf < 8; nf++){ o[nf][0]=o[nf][1]=o[nf][2]=o[nf][3]=0.f; }
    float mrun0 = -1e30f, mrun1 = -1e30f, l0 = 0.f, l1 = 0.f;

    const float* kbase = g_k + bh*N_*D_;            // compacted [j][d]
    const float* vbase = g_v + bh*(size_t)D_*N_;    // compacted [d][j]
    const float* ar0   = alibi + (bh*N_ + r0)*(size_t)N_;
    const float* ar1   = ar0 + (size_t)8*N_;
    const int*   ibase = g_idx + b*N_;

    auto load_kv = [&](int j0, int buf){
        float* dK = KsB + buf*KV_BUF;
        float* dV = VsB + buf*KV_BUF;
        #pragma unroll
        for (int i = 0; i < 4; i++){
            int id  = tid + i*256;
            int row = id >> 4;
            int c4  = (id & 15) << 2;
            cp_async16(&dK[row*KSTR + c4], kbase + (size_t)(j0+row)*64 + c4);
            cp_async16(&dV[row*KSTR + c4], vbase + (size_t)row*N_ + j0 + c4);
        }
        cp_commit();
    };

    load_kv(0, 0);
    if (ntiles > 1) load_kv(64, 1);

    for (int it = 0; it < ntiles; it++){
        const int j0 = it << 6;
        if (it + 1 < ntiles) cp_wait<1>(); else cp_wait<0>();
        __syncthreads();

        const float* Ks = KsB + (it & 1)*KV_BUF;
        const float* Vs = VsB + (it & 1)*KV_BUF;

        // idx pairs for this thread's 16 columns (latency hidden under QK)
        int2 ix[8];
        #pragma unroll
        for (int nf = 0; nf < 8; nf++)
            ix[nf] = *(const int2*)&ibase[j0 + nf*8 + t2];

        // S = Q' @ K^T
        float s[8][4];
        #pragma unroll
        for (int nf = 0; nf < 8; nf++){ s[nf][0]=s[nf][1]=s[nf][2]=s[nf][3]=0.f; }
        #pragma unroll
        for (int ks = 0; ks < 8; ks++){
            #pragma unroll
            for (int nf = 0; nf < 8; nf++){
                float2 bp = *(const float2*)&Ks[(nf*8 + R)*KSTR + ks*8 + t2];
                mma8(s[nf], qa[ks], bp.x, bp.y);
            }
        }

        // gather alibi directly into S (post-QK add; *log2e)
        #pragma unroll
        for (int nf = 0; nf < 8; nf++){
            float a00 = ar0[ix[nf].x];
            float a01 = ar0[ix[nf].y];
            float a10 = ar1[ix[nf].x];
            float a11 = ar1[ix[nf].y];
            s[nf][0] = fmaf(a00, LOG2E, s[nf][0]);
            s[nf][1] = fmaf(a01, LOG2E, s[nf][1]);
            s[nf][2] = fmaf(a10, LOG2E, s[nf][2]);
            s[nf][3] = fmaf(a11, LOG2E, s[nf][3]);
        }

        // tail mask: columns beyond valid
        int rem = valid - j0;
        if (rem < 64){
            #pragma unroll
            for (int nf = 0; nf < 8; nf++){
                int c = nf*8 + t2;
                if (c   >= rem){ s[nf][0] = NEG_INF; s[nf][2] = NEG_INF; }
                if (c+1 >= rem){ s[nf][1] = NEG_INF; s[nf][3] = NEG_INF; }
            }
        }

        // online softmax in log2 domain (rows live in quads)
        float mx0 = -INFINITY, mx1 = -INFINITY;
        #pragma unroll
        for (int nf = 0; nf < 8; nf++){
            mx0 = fmaxf(mx0, fmaxf(s[nf][0], s[nf][1]));
            mx1 = fmaxf(mx1, fmaxf(s[nf][2], s[nf][3]));
        }
        mx0 = fmaxf(mx0, __shfl_xor_sync(0xffffffffu, mx0, 1));
        mx0 = fmaxf(mx0, __shfl_xor_sync(0xffffffffu, mx0, 2));
        mx1 = fmaxf(mx1, __shfl_xor_sync(0xffffffffu, mx1, 1));
        mx1 = fmaxf(mx1, __shfl_xor_sync(0xffffffffu, mx1, 2));
        float mn0 = fmaxf(mrun0, mx0);
        float mn1 = fmaxf(mrun1, mx1);
        float al0 = ex2(mrun0 - mn0);
        float al1 = ex2(mrun1 - mn1);
        mrun0 = mn0; mrun1 = mn1;

        float ls0 = 0.f, ls1 = 0.f;
        #pragma unroll
        for (int nf = 0; nf < 8; nf++){
            s[nf][0] = ex2(s[nf][0] - mn0); ls0 += s[nf][0];
            s[nf][1] = ex2(s[nf][1] - mn0); ls0 += s[nf][1];
            s[nf][2] = ex2(s[nf][2] - mn1); ls1 += s[nf][2];
            s[nf][3] = ex2(s[nf][3] - mn1); ls1 += s[nf][3];
            o[nf][0] *= al0; o[nf][1] *= al0; o[nf][2] *= al1; o[nf][3] *= al1;
        }
        ls0 += __shfl_xor_sync(0xffffffffu, ls0, 1);
        ls0 += __shfl_xor_sync(0xffffffffu, ls0, 2);
        ls1 += __shfl_xor_sync(0xffffffffu, ls1, 1);
        ls1 += __shfl_xor_sync(0xffffffffu, ls1, 2);
        l0 = l0*al0 + ls0;
        l1 = l1*al1 + ls1;

        // O += P @ V (S fragment direct as A; V^T supplies mu-permuted keys)
        #pragma unroll
        for (int ks = 0; ks < 8; ks++){
            float pa[4];
            pa[0] = to_tf32(s[ks][0]);
            pa[1] = to_tf32(s[ks][2]);
            pa[2] = to_tf32(s[ks][1]);
            pa[3] = to_tf32(s[ks][3]);
            #pragma unroll
            for (int nf = 0; nf < 8; nf++){
                float2 bp = *(const float2*)&Vs[(nf*8 + R)*KSTR + ks*8 + t2];
                mma8(o[nf], pa, bp.x, bp.y);
            }
        }
        __syncthreads();
        if (it + 2 < ntiles) load_kv((it+2) << 6, it & 1);
    }

    // epilogue: normalized O -> g_att as tf32, column-permuted
    const float inv0 = 1.0f / l0;
    const float inv1 = 1.0f / l1;
    float* orow0 = g_att + ((size_t)(b*N_ + r0))*C_;
    float* orow1 = orow0 + (size_t)8*C_;
    #pragma unroll
    for (int nf = 0; nf < 8; nf++){
        int c = h*64 + nf*8 + t2;
        orow0[perm8(c)]   = to_tf32(o[nf][0]*inv0);
        orow0[perm8(c+1)] = to_tf32(o[nf][1]*inv0);
        orow1[perm8(c)]   = to_tf32(o[nf][2]*inv1);
        orow1[perm8(c+1)] = to_tf32(o[nf][3]*inv1);
    }
}

// ---------------------------------------------------------------------------
extern "C" void kernel_launch(void* const* d_in, const int* in_sizes, int n_in,
                              void* d_out, int out_size)
{
    (void)in_sizes; (void)n_in; (void)out_size;
    const float* x      = (const float*)d_in[0];
    const int*   pmask  = (const int*)d_in[1];
    const float* alibi  = (const float*)d_in[2];
    const float* qkv_w  = (const float*)d_in[3];
    const float* qkv_b  = (const float*)d_in[4];
    const float* proj_w = (const float*)d_in[5];
    const float* proj_b = (const float*)d_in[6];
    float*       out    = (float*)d_out;

    const int GEMM_SMEM = (2*ABUF + 2*BBUF) * 4;              // 71680 B
    const int ATTN_SMEM = (4*KV_BUF) * 4;                     // 73728 B
    cudaFuncSetAttribute(gemm_tf32_kernel, cudaFuncAttributeMaxDynamicSharedMemorySize, GEMM_SMEM);
    cudaFuncSetAttribute(attn_kernel, cudaFuncAttributeMaxDynamicSharedMemorySize, ATTN_SMEM);

    float *att_ptr = nullptr, *xc_ptr = nullptr, *wqkvT_ptr = nullptr, *wprojT_ptr = nullptr;
    cudaGetSymbolAddress((void**)&att_ptr,    g_att);
    cudaGetSymbolAddress((void**)&xc_ptr,     g_xc);
    cudaGetSymbolAddress((void**)&wqkvT_ptr,  g_wqkvT);
    cudaGetSymbolAddress((void**)&wprojT_ptr, g_wprojT);

    // 0) one-time: mask scan + tf32/permute conversions
    build_index<<<B_, 256>>>(pmask);
    {
        int n8 = (B_*N_*C_) / 8;
        cvt_perm_rows<<<(n8 + 255)/256, 256>>>(x, xc_ptr, n8);
        int nq = C_ * 3*C_;
        cvt_perm_T<<<(nq + 255)/256, 256>>>(qkv_w, wqkvT_ptr, C_, 3*C_);
        int np = C_ * C_;
        cvt_perm_T<<<(np + 255)/256, 256>>>(proj_w, wprojT_ptr, C_, C_);
    }
    // 1a) Q projection over all rows -> g_q (d-perm tf32)
    gemm_tf32_kernel<<<dim3(768/96, 8192/128), 128, GEMM_SMEM>>>(
        xc_ptr, wqkvT_ptr, qkv_b, nullptr, 8192, 768, 768, 1);
    // 1b) K/V projection over compacted survivor rows only (A gathered by idx)
    gemm_tf32_kernel<<<dim3(1536/96, B_*16), 128, GEMM_SMEM>>>(
        xc_ptr, wqkvT_ptr + (size_t)768*768, qkv_b + 768, nullptr, 8192, 768, 1536, 2);
    // 2) fused attention over compacted keys -> g_att (tf32, c-permuted)
    attn_kernel<<<dim3(N_/128, H_, B_), 256, ATTN_SMEM>>>(alibi);
    // 3) output projection + bias -> d_out (fp32)
    gemm_tf32_kernel<<<dim3(768/96, 8192/128), 128, GEMM_SMEM>>>(
        att_ptr, wprojT_ptr, proj_b, out, 8192, 768, 768, 0);
}